// round 12
// baseline (speedup 1.0000x reference)
#include <cuda_runtime.h>
#include <cuda_bf16.h>
#include <math.h>
#include <stdint.h>

#define BATCH   8192
#define P_DIM   512
#define DM      256     // D_MODEL
#define DI      512     // D_INNER
#define DS      16
#define ADIM    64
#define KSPLIT  4

typedef __nv_bfloat16 bf16;

// ---------------- fp32 scratch ----------------
__device__ float g_U  [BATCH * DI];
__device__ float g_Zs [BATCH * DI];
__device__ float g_xd [KSPLIT * BATCH * 48];   // split-K partials
__device__ float g_hb [128];

// ---------------- bf16 hi/lo planes (activations) ----------------
__device__ __align__(256) bf16 g_ph[BATCH * P_DIM], g_pl[BATCH * P_DIM];
__device__ __align__(256) bf16 g_xh[BATCH * DM],    g_xl[BATCH * DM];
__device__ __align__(256) bf16 g_Uh[BATCH * DI],    g_Ul[BATCH * DI];
__device__ __align__(256) bf16 g_Yh[BATCH * DI],    g_Yl[BATCH * DI];

// ---------------- bf16 hi/lo planes (weights) ----------------
__device__ __align__(256) bf16 g_Winh[DM * P_DIM],   g_Winl[DM * P_DIM];
__device__ __align__(256) bf16 g_iph [2 * DI * DM],  g_ipl [2 * DI * DM];
__device__ __align__(256) bf16 g_xph [64 * DI],      g_xpl [64 * DI];
__device__ __align__(256) bf16 g_hwch[128 * DI],     g_hwcl[128 * DI];   // fused head W

__device__ __forceinline__ float siluf(float x) { return x / (1.f + __expf(-x)); }
__device__ __forceinline__ float softplusf(float x) {
    return (x > 20.f) ? x : log1pf(__expf(x));
}
__device__ __forceinline__ uint32_t smem_u32(const void* p) {
    uint32_t a;
    asm("{ .reg .u64 t; cvta.to.shared.u64 t, %1; cvt.u32.u64 %0, t; }"
        : "=r"(a) : "l"(p));
    return a;
}
__device__ __forceinline__ void ldsm4(uint32_t addr, uint32_t r[4]) {
    asm volatile("ldmatrix.sync.aligned.m8n8.x4.shared.b16 {%0,%1,%2,%3}, [%4];"
                 : "=r"(r[0]), "=r"(r[1]), "=r"(r[2]), "=r"(r[3]) : "r"(addr));
}
__device__ __forceinline__ void mma16816(float c[4], const uint32_t a[4],
                                         uint32_t b0, uint32_t b1) {
    asm volatile(
        "mma.sync.aligned.m16n8k16.row.col.f32.bf16.bf16.f32 "
        "{%0,%1,%2,%3}, {%4,%5,%6,%7}, {%8,%9}, {%0,%1,%2,%3};"
        : "+f"(c[0]), "+f"(c[1]), "+f"(c[2]), "+f"(c[3])
        : "r"(a[0]), "r"(a[1]), "r"(a[2]), "r"(a[3]), "r"(b0), "r"(b1));
}
#define CP_ASYNC16(dst, src) \
    asm volatile("cp.async.cg.shared.global [%0], [%1], 16;" :: "r"(dst), "l"(src))
#define CP_COMMIT()  asm volatile("cp.async.commit_group;" ::: "memory")
#define CP_WAIT1()   asm volatile("cp.async.wait_group 1;" ::: "memory")
#define CP_WAIT0()   asm volatile("cp.async.wait_group 0;" ::: "memory")

__device__ __forceinline__ void wsplit2(bf16* H, bf16* L, size_t off,
                                        float v0, float v1) {
    bf16 h0 = __float2bfloat16(v0), h1 = __float2bfloat16(v1);
    bf16 l0 = __float2bfloat16(v0 - __bfloat162float(h0));
    bf16 l1 = __float2bfloat16(v1 - __bfloat162float(h1));
    *reinterpret_cast<__nv_bfloat162*>(H + off) = __halves2bfloat162(h0, h1);
    *reinterpret_cast<__nv_bfloat162*>(L + off) = __halves2bfloat162(l0, l1);
}
__device__ __forceinline__ void wsplit1(bf16* H, bf16* L, size_t off, float v) {
    bf16 h = __float2bfloat16(v);
    H[off] = h;
    L[off] = __float2bfloat16(v - __bfloat162float(h));
}

// ====== bf16x3 tensor GEMM, 3-stage cp.async pipeline ======
// Tile 128(M) x 64(N) x 32(K). 256 thr = 8 warps (4m x 2n), 32x32/warp.
// EPI: 0 +bias -> x planes | 1 in_proj split | 3 fused heads -> out
//      4 xdbl partial (grid.z = split, n<48)
#define BUFSZ 30720
#define GSMEM (3 * BUFSZ)     // 92160

template<int EPI>
__global__ void __launch_bounds__(256)
mma_gemm(const bf16* __restrict__ Ah, const bf16* __restrict__ Al,
         const bf16* __restrict__ Bh, const bf16* __restrict__ Bl,
         int K, int lda,
         float* __restrict__ C, const float* __restrict__ e0,
         const float* __restrict__ e1, float* __restrict__ e2,
         bf16* __restrict__ Ch, bf16* __restrict__ Cl)
{
    constexpr int LDS = 80;
    extern __shared__ __align__(16) uint8_t dsm[];
    const uint32_t sb = smem_u32(dsm);

    const int tid  = threadIdx.x;
    const int lane = tid & 31, wid = tid >> 5;
    const int wm = wid & 3, wn = wid >> 2;
    const int m0 = blockIdx.y * 128, n0 = blockIdx.x * 64;
    const int kOff = blockIdx.z * K;
    const int lr = lane & 7, sub = lane >> 3;

    float acc[2][4][4];
#pragma unroll
    for (int i = 0; i < 2; i++)
#pragma unroll
        for (int j = 0; j < 4; j++)
#pragma unroll
            for (int l = 0; l < 4; l++) acc[i][j][l] = 0.f;

    const int nchunks = K >> 5;

    auto copy_chunk = [&](int c, int buf) {
        const int kg = kOff + (c << 5);
        const uint32_t b = sb + buf * BUFSZ;
#pragma unroll
        for (int j = 0; j < 2; ++j) {
            const int idx = tid + j * 256;
            const int row = idx >> 2, cc = idx & 3;
            const size_t go = (size_t)(m0 + row) * lda + kg + cc * 8;
            const uint32_t so = b + row * LDS + cc * 16;
            CP_ASYNC16(so,         Ah + go);
            CP_ASYNC16(so + 10240, Al + go);
        }
        {
            const int row = tid >> 2, cc = tid & 3;
            const size_t go = (size_t)(n0 + row) * lda + kg + cc * 8;
            const uint32_t so = b + 20480 + row * LDS + cc * 16;
            CP_ASYNC16(so,        Bh + go);
            CP_ASYNC16(so + 5120, Bl + go);
        }
        CP_COMMIT();
    };

    copy_chunk(0, 0);
    if (nchunks > 1) copy_chunk(1, 1);

    int buf = 0, nbuf = 2 == nchunks ? 0 : 2;   // next buffer to fill (c+2)%3
    for (int c = 0; c < nchunks; ++c) {
        if (c + 1 < nchunks) CP_WAIT1(); else CP_WAIT0();
        __syncthreads();
        if (c + 2 < nchunks) {
            copy_chunk(c + 2, nbuf);
        }

        const uint32_t b   = sb + buf * BUFSZ;
        const uint32_t aAh = b, aAl = b + 10240;
        const uint32_t aBh = b + 20480, aBl = b + 25600;

#pragma unroll
        for (int ks = 0; ks < 2; ++ks) {
            const int kb = ks * 32;
            uint32_t Afh[2][4], Afl[2][4];
            {
                const int rowoff = ((sub & 1) << 3) + lr;
                const int kboff  = kb + ((sub >> 1) << 4);
#pragma unroll
                for (int mt = 0; mt < 2; ++mt) {
                    const uint32_t off =
                        (uint32_t)((wm * 32 + mt * 16 + rowoff) * LDS + kboff);
                    ldsm4(aAh + off, Afh[mt]);
                    ldsm4(aAl + off, Afl[mt]);
                }
            }
            uint32_t Bfh[2][4], Bfl[2][4];
            {
                const int nrow  = ((sub >> 1) << 3) + lr;
                const int kboff = kb + ((sub & 1) << 4);
#pragma unroll
                for (int np = 0; np < 2; ++np) {
                    const uint32_t off =
                        (uint32_t)((wn * 32 + np * 16 + nrow) * LDS + kboff);
                    ldsm4(aBh + off, Bfh[np]);
                    ldsm4(aBl + off, Bfl[np]);
                }
            }
#pragma unroll
            for (int mt = 0; mt < 2; ++mt)
#pragma unroll
                for (int nt = 0; nt < 4; ++nt) {
                    const uint32_t bh0 = Bfh[nt >> 1][(nt & 1) * 2];
                    const uint32_t bh1 = Bfh[nt >> 1][(nt & 1) * 2 + 1];
                    const uint32_t bl0 = Bfl[nt >> 1][(nt & 1) * 2];
                    const uint32_t bl1 = Bfl[nt >> 1][(nt & 1) * 2 + 1];
                    mma16816(acc[mt][nt], Afh[mt], bh0, bh1);
                    mma16816(acc[mt][nt], Afh[mt], bl0, bl1);
                    mma16816(acc[mt][nt], Afl[mt], bh0, bh1);
                }
        }
        buf  = (buf == 2)  ? 0 : buf + 1;
        nbuf = (nbuf == 2) ? 0 : nbuf + 1;
    }

    // ---- epilogue ----
    const int tg = lane >> 2, tc = lane & 3;
#pragma unroll
    for (int mt = 0; mt < 2; ++mt) {
#pragma unroll
        for (int half = 0; half < 2; ++half) {
            const int m = m0 + wm * 32 + mt * 16 + tg + half * 8;
#pragma unroll
            for (int nt = 0; nt < 4; ++nt) {
                const int n = n0 + wn * 32 + nt * 8 + tc * 2;
                float v0 = acc[mt][nt][half * 2 + 0];
                float v1 = acc[mt][nt][half * 2 + 1];
                if (EPI == 0) {                      // x: +bias -> planes
                    v0 += e0[n]; v1 += e0[n + 1];
                    wsplit2(Ch, Cl, (size_t)m * DM + n, v0, v1);
                } else if (EPI == 1) {               // in_proj split
                    if (n < DI) {
                        v0 = siluf(v0 * e0[n * 4 + 3] + e1[n]);
                        v1 = siluf(v1 * e0[(n + 1) * 4 + 3] + e1[n + 1]);
                        *reinterpret_cast<float2*>(C + (size_t)m * DI + n) =
                            make_float2(v0, v1);
                        wsplit2(Ch, Cl, (size_t)m * DI + n, v0, v1);
                    } else {
                        *reinterpret_cast<float2*>(e2 + (size_t)m * DI + (n - DI)) =
                            make_float2(siluf(v0), siluf(v1));
                    }
                } else if (EPI == 3) {               // fused heads -> out
                    v0 += e0[n]; v1 += e0[n + 1];
                    if (n < ADIM) {
                        *reinterpret_cast<float2*>(e2 + (size_t)m * ADIM + n) =
                            make_float2(tanhf(v0), tanhf(v1));
                    } else {
                        v0 = fminf(fmaxf(v0, -5.f), 2.f);
                        v1 = fminf(fmaxf(v1, -5.f), 2.f);
                        *reinterpret_cast<float2*>(
                            e2 + (size_t)BATCH * ADIM + (size_t)m * ADIM + (n - ADIM)) =
                            make_float2(v0, v1);
                    }
                } else {                             // EPI 4: xdbl partial
                    if (n < 48)
                        *reinterpret_cast<float2*>(
                            C + (size_t)blockIdx.z * BATCH * 48 + (size_t)m * 48 + n) =
                            make_float2(v0, v1);
                }
            }
        }
    }
}

// ---------------- fused SSM pointwise -> Y bf16 planes ----------------
__global__ void __launch_bounds__(256)
mamba_pointwise(const float* __restrict__ xdbl, const float* __restrict__ dt_w,
                const float* __restrict__ dt_b, const float* __restrict__ Dskip,
                const float* __restrict__ U, const float* __restrict__ Zs,
                bf16* __restrict__ Yh, bf16* __restrict__ Yl)
{
    constexpr int NB = 16;
    __shared__ float s_xd[NB][48];
    __shared__ float s_bc[NB];
    const int b0 = blockIdx.x * NB;
    const int tid = threadIdx.x;

    for (int i = tid; i < NB * 48; i += 256) {
        const size_t off = (size_t)(b0 + i / 48) * 48 + (i % 48);
        float s = xdbl[off];
#pragma unroll
        for (int p = 1; p < KSPLIT; ++p)
            s += xdbl[(size_t)p * BATCH * 48 + off];
        s_xd[i / 48][i % 48] = s;
    }
    __syncthreads();
    if (tid < NB) {
        float s = 0.f;
#pragma unroll
        for (int n = 0; n < DS; n++) s += s_xd[tid][16 + n] * s_xd[tid][32 + n];
        s_bc[tid] = s;
    }
    __syncthreads();

#pragma unroll 1
    for (int dd = 0; dd < DI / 256; dd++) {
        const int d = tid + dd * 256;
        const float4 w0 = *reinterpret_cast<const float4*>(dt_w + d * 16 + 0);
        const float4 w1 = *reinterpret_cast<const float4*>(dt_w + d * 16 + 4);
        const float4 w2 = *reinterpret_cast<const float4*>(dt_w + d * 16 + 8);
        const float4 w3 = *reinterpret_cast<const float4*>(dt_w + d * 16 + 12);
        const float bias = dt_b[d];
        const float dsk  = Dskip[d];
#pragma unroll
        for (int bb = 0; bb < NB; bb++) {
            const int b = b0 + bb;
            const float* xd = s_xd[bb];
            float a = bias;
            a = fmaf(w0.x, xd[0],  a); a = fmaf(w0.y, xd[1],  a);
            a = fmaf(w0.z, xd[2],  a); a = fmaf(w0.w, xd[3],  a);
            a = fmaf(w1.x, xd[4],  a); a = fmaf(w1.y, xd[5],  a);
            a = fmaf(w1.z, xd[6],  a); a = fmaf(w1.w, xd[7],  a);
            a = fmaf(w2.x, xd[8],  a); a = fmaf(w2.y, xd[9],  a);
            a = fmaf(w2.z, xd[10], a); a = fmaf(w2.w, xd[11], a);
            a = fmaf(w3.x, xd[12], a); a = fmaf(w3.y, xd[13], a);
            a = fmaf(w3.z, xd[14], a); a = fmaf(w3.w, xd[15], a);
            const float delta = softplusf(a);
            const float u = U[(size_t)b * DI + d];
            const float y = u * fmaf(delta, s_bc[bb], dsk) * Zs[(size_t)b * DI + d];
            wsplit1(Yh, Yl, (size_t)b * DI + d, y);
        }
    }
}

// ---------------- weight prep (W_in, in_proj, x_proj, head bias) ----------------
__global__ void prep(const float* __restrict__ W_in, const float* __restrict__ ip,
                     const float* __restrict__ xp,
                     const float* __restrict__ mu_b, const float* __restrict__ ls_b,
                     float* __restrict__ hb)
{
    const int i = blockIdx.x * 256 + threadIdx.x;       // 0..425983
    if (i < 131072) {
        wsplit1(g_Winh, g_Winl, i, W_in[i]);
    } else if (i < 393216) {
        const int j = i - 131072;
        wsplit1(g_iph, g_ipl, j, ip[j]);
    } else if (i < 425984) {
        const int j = i - 393216;
        wsplit1(g_xph, g_xpl, j, (j < 48 * DI) ? xp[j] : 0.f);
    }
    if (i < 128) hb[i] = (i < ADIM) ? mu_b[i] : ls_b[i - ADIM];
}

// ---------------- fused head weight: Whc = [mu_w;ls_w] @ out_proj ----------------
__global__ void __launch_bounds__(512)
fuse_heads(const float* __restrict__ mu_w, const float* __restrict__ ls_w,
           const float* __restrict__ op)
{
    const int i = blockIdx.x;            // 0..127
    const int j = threadIdx.x;           // 0..511
    const float* wrow = (i < ADIM) ? (mu_w + (size_t)i * DM)
                                   : (ls_w + (size_t)(i - ADIM) * DM);
    float s = 0.f;
#pragma unroll 8
    for (int k = 0; k < DM; ++k)
        s = fmaf(wrow[k], op[(size_t)k * DI + j], s);
    wsplit1(g_hwch, g_hwcl, (size_t)i * DI + j, s);
}

// ---------------- perception -> planes ----------------
__global__ void conv_perc(const float* __restrict__ src)
{
    const size_t i = ((size_t)blockIdx.x * 256 + threadIdx.x) * 4;
    const float4 v = *reinterpret_cast<const float4*>(src + i);
    wsplit2(g_ph, g_pl, i,     v.x, v.y);
    wsplit2(g_ph, g_pl, i + 2, v.z, v.w);
}

// ---------------- launch ----------------
extern "C" void kernel_launch(void* const* d_in, const int* in_sizes, int n_in,
                              void* d_out, int out_size)
{
    const float* perception = (const float*)d_in[0];
    const float* W_in       = (const float*)d_in[1];
    const float* b_in       = (const float*)d_in[2];
    const float* mu_w       = (const float*)d_in[3];
    const float* mu_b       = (const float*)d_in[4];
    const float* ls_w       = (const float*)d_in[5];
    const float* ls_b       = (const float*)d_in[6];
    const float* in_proj_w  = (const float*)d_in[7];
    const float* conv_w     = (const float*)d_in[8];
    const float* conv_b     = (const float*)d_in[9];
    const float* x_proj_w   = (const float*)d_in[10];
    const float* dt_proj_w  = (const float*)d_in[11];
    const float* dt_proj_b  = (const float*)d_in[12];
    const float* Dskip      = (const float*)d_in[14];
    const float* out_proj_w = (const float*)d_in[15];
    float* out = (float*)d_out;

    float *pU, *pZs, *pxd, *phb;
    cudaGetSymbolAddress((void**)&pU,  g_U);
    cudaGetSymbolAddress((void**)&pZs, g_Zs);
    cudaGetSymbolAddress((void**)&pxd, g_xd);
    cudaGetSymbolAddress((void**)&phb, g_hb);

    bf16 *ph_, *pl_, *xh, *xl, *Uh, *Ul, *Yh, *Yl;
    bf16 *Wh, *Wl, *ih, *il, *xph_, *xpl_, *hwch, *hwcl;
    cudaGetSymbolAddress((void**)&ph_, g_ph);  cudaGetSymbolAddress((void**)&pl_, g_pl);
    cudaGetSymbolAddress((void**)&xh,  g_xh);  cudaGetSymbolAddress((void**)&xl,  g_xl);
    cudaGetSymbolAddress((void**)&Uh,  g_Uh);  cudaGetSymbolAddress((void**)&Ul,  g_Ul);
    cudaGetSymbolAddress((void**)&Yh,  g_Yh);  cudaGetSymbolAddress((void**)&Yl,  g_Yl);
    cudaGetSymbolAddress((void**)&Wh,  g_Winh);cudaGetSymbolAddress((void**)&Wl,  g_Winl);
    cudaGetSymbolAddress((void**)&ih,  g_iph); cudaGetSymbolAddress((void**)&il,  g_ipl);
    cudaGetSymbolAddress((void**)&xph_,g_xph); cudaGetSymbolAddress((void**)&xpl_,g_xpl);
    cudaGetSymbolAddress((void**)&hwch,g_hwch);cudaGetSymbolAddress((void**)&hwcl,g_hwcl);

    cudaFuncSetAttribute((const void*)mma_gemm<0>, cudaFuncAttributeMaxDynamicSharedMemorySize, GSMEM);
    cudaFuncSetAttribute((const void*)mma_gemm<1>, cudaFuncAttributeMaxDynamicSharedMemorySize, GSMEM);
    cudaFuncSetAttribute((const void*)mma_gemm<3>, cudaFuncAttributeMaxDynamicSharedMemorySize, GSMEM);
    cudaFuncSetAttribute((const void*)mma_gemm<4>, cudaFuncAttributeMaxDynamicSharedMemorySize, GSMEM);

    // 0) prep: weight splits, fused head weight, perception split
    prep<<<1664, 256>>>(W_in, in_proj_w, x_proj_w, mu_b, ls_b, phb);
    fuse_heads<<<128, 512>>>(mu_w, ls_w, out_proj_w);
    conv_perc<<<4096, 256>>>(perception);

    // 1) x = perc @ W_in^T + b        (8192x256, K=512) -> x planes
    mma_gemm<0><<<dim3(4, 64), 256, GSMEM>>>(
        ph_, pl_, Wh, Wl, P_DIM, P_DIM, nullptr, b_in, nullptr, nullptr, xh, xl);

    // 2) xz = x @ in_proj^T (N=1024)  -> U fp32+planes / Zs fp32
    mma_gemm<1><<<dim3(16, 64), 256, GSMEM>>>(
        xh, xl, ih, il, DM, DM, pU, conv_w, conv_b, pZs, Uh, Ul);

    // 3) x_dbl partials, split-K=4    (K=128 each, lda=512)
    mma_gemm<4><<<dim3(1, 64, KSPLIT), 256, GSMEM>>>(
        Uh, Ul, xph_, xpl_, DI / KSPLIT, DI, pxd, nullptr, nullptr, nullptr, nullptr, nullptr);

    // 4) pointwise -> Y planes
    mamba_pointwise<<<BATCH / 16, 256>>>(pxd, dt_proj_w, dt_proj_b, Dskip,
                                         pU, pZs, Yh, Yl);

    // 5) fused heads: [mu|log_std] = Y @ Whc^T + hb  (8192x128, K=512) -> out
    mma_gemm<3><<<dim3(2, 64), 256, GSMEM>>>(
        Yh, Yl, hwch, hwcl, DI, DI, nullptr, phb, nullptr, out, nullptr, nullptr);
}

// round 14
// speedup vs baseline: 1.0941x; 1.0941x over previous
#include <cuda_runtime.h>
#include <cuda_bf16.h>
#include <math.h>
#include <stdint.h>

#define BATCH   8192
#define P_DIM   512
#define DM      256     // D_MODEL
#define DI      512     // D_INNER
#define DS      16
#define ADIM    64

typedef __nv_bfloat16 bf16;

// ---------------- fp32 scratch ----------------
__device__ float g_U  [BATCH * DI];
__device__ float g_Zs [BATCH * DI];
__device__ float g_xd [2 * BATCH * 48];        // split-K partials
__device__ float g_hb [128];
__device__ __align__(256) float g_xt [BATCH * DM];     // x, tf32-rounded fp32
__device__ __align__(256) float g_ipt[2 * DI * DM];    // in_proj_w, tf32-rounded

// ---------------- bf16 hi/lo planes ----------------
__device__ __align__(256) bf16 g_ph[BATCH * P_DIM], g_pl[BATCH * P_DIM];
__device__ __align__(256) bf16 g_Uh[BATCH * DI],    g_Ul[BATCH * DI];
__device__ __align__(256) bf16 g_Yh[BATCH * DI],    g_Yl[BATCH * DI];
__device__ __align__(256) bf16 g_Winh[DM * P_DIM],  g_Winl[DM * P_DIM];
__device__ __align__(256) bf16 g_xph [64 * DI],     g_xpl [64 * DI];
__device__ __align__(256) bf16 g_hwch[128 * DI],    g_hwcl[128 * DI];

__device__ __forceinline__ float siluf(float x) { return x / (1.f + __expf(-x)); }
__device__ __forceinline__ float softplusf(float x) {
    return (x > 20.f) ? x : log1pf(__expf(x));
}
__device__ __forceinline__ float tf32r(float v) {
    uint32_t r;
    asm("cvt.rna.tf32.f32 %0, %1;" : "=r"(r) : "f"(v));
    return __uint_as_float(r);
}
__device__ __forceinline__ uint32_t smem_u32(const void* p) {
    uint32_t a;
    asm("{ .reg .u64 t; cvta.to.shared.u64 t, %1; cvt.u32.u64 %0, t; }"
        : "=r"(a) : "l"(p));
    return a;
}
__device__ __forceinline__ void ldsm4(uint32_t addr, uint32_t r[4]) {
    asm volatile("ldmatrix.sync.aligned.m8n8.x4.shared.b16 {%0,%1,%2,%3}, [%4];"
                 : "=r"(r[0]), "=r"(r[1]), "=r"(r[2]), "=r"(r[3]) : "r"(addr));
}
__device__ __forceinline__ void mma_bf(float c[4], const uint32_t a[4],
                                       uint32_t b0, uint32_t b1) {
    asm volatile(
        "mma.sync.aligned.m16n8k16.row.col.f32.bf16.bf16.f32 "
        "{%0,%1,%2,%3}, {%4,%5,%6,%7}, {%8,%9}, {%0,%1,%2,%3};"
        : "+f"(c[0]), "+f"(c[1]), "+f"(c[2]), "+f"(c[3])
        : "r"(a[0]), "r"(a[1]), "r"(a[2]), "r"(a[3]), "r"(b0), "r"(b1));
}
__device__ __forceinline__ void mma_tf(float c[4], const uint32_t a[4],
                                       uint32_t b0, uint32_t b1) {
    asm volatile(
        "mma.sync.aligned.m16n8k8.row.col.f32.tf32.tf32.f32 "
        "{%0,%1,%2,%3}, {%4,%5,%6,%7}, {%8,%9}, {%0,%1,%2,%3};"
        : "+f"(c[0]), "+f"(c[1]), "+f"(c[2]), "+f"(c[3])
        : "r"(a[0]), "r"(a[1]), "r"(a[2]), "r"(a[3]), "r"(b0), "r"(b1));
}
#define CP_ASYNC16(dst, src) \
    asm volatile("cp.async.cg.shared.global [%0], [%1], 16;" :: "r"(dst), "l"(src))
#define CP_COMMIT()  asm volatile("cp.async.commit_group;" ::: "memory")
#define CP_WAIT0()   asm volatile("cp.async.wait_group 0;" ::: "memory")

__device__ __forceinline__ void wsplit2(bf16* H, bf16* L, size_t off,
                                        float v0, float v1) {
    bf16 h0 = __float2bfloat16(v0), h1 = __float2bfloat16(v1);
    bf16 l0 = __float2bfloat16(v0 - __bfloat162float(h0));
    bf16 l1 = __float2bfloat16(v1 - __bfloat162float(h1));
    *reinterpret_cast<__nv_bfloat162*>(H + off) = __halves2bfloat162(h0, h1);
    *reinterpret_cast<__nv_bfloat162*>(L + off) = __halves2bfloat162(l0, l1);
}
__device__ __forceinline__ void wsplit1(bf16* H, bf16* L, size_t off, float v) {
    bf16 h = __float2bfloat16(v);
    H[off] = h;
    L[off] = __float2bfloat16(v - __bfloat162float(h));
}

// ====== tensor GEMM: C[m,n] = sum_k A[m,k] * W[n,k] ======
// Tile 128(M) x 64(N) x 32(K). 256 thr = 8 warps (4m x 2n), 32x32/warp.
// 2-stage cp.async pipeline (R11-proven).
// PREC 0: bf16x3 (A/B hi+lo planes, 3 MMA/acc/k16)
// PREC 2: tf32x1 (A/B pre-rounded fp32, 1 MMA/acc/k8)
// EPI: 0 +bias -> tf32 x | 1 in_proj split | 3 fused heads -> out
//      4 xdbl partial (grid.z split, n<48)
template<int EPI, int PREC>
__global__ void __launch_bounds__(256)
mma_gemm(const void* __restrict__ Ahv, const void* __restrict__ Alv,
         const void* __restrict__ Bhv, const void* __restrict__ Blv,
         int K, int lda,
         float* __restrict__ C, const float* __restrict__ e0,
         const float* __restrict__ e1, float* __restrict__ e2,
         bf16* __restrict__ Ch, bf16* __restrict__ Cl)
{
    constexpr bool TF   = (PREC == 2);
    constexpr int  LDS  = TF ? 144 : 80;
    constexpr int  BOFF = TF ? 18432 : 20480;          // B region start
    constexpr int  BUFB = TF ? 27648 : 30720;          // bytes per stage

    extern __shared__ __align__(16) uint8_t dsm[];
    const uint32_t sb = smem_u32(dsm);

    const int tid  = threadIdx.x;
    const int lane = tid & 31, wid = tid >> 5;
    const int wm = wid & 3, wn = wid >> 2;
    const int m0 = blockIdx.y * 128, n0 = blockIdx.x * 64;
    const int kOff = blockIdx.z * K;
    const int lr = lane & 7, sub = lane >> 3;

    float acc[2][4][4];
#pragma unroll
    for (int i = 0; i < 2; i++)
#pragma unroll
        for (int j = 0; j < 4; j++)
#pragma unroll
            for (int l = 0; l < 4; l++) acc[i][j][l] = 0.f;

    const int nchunks = K >> 5;

    auto copy_chunk = [&](int c, int buf) {
        const int kg = kOff + (c << 5);
        const uint32_t b = sb + buf * BUFB;
        if (TF) {
            const float* Af = (const float*)Ahv;
            const float* Bf = (const float*)Bhv;
#pragma unroll
            for (int j = 0; j < 4; ++j) {                // A: 128 rows x 128B
                const int idx = tid + j * 256;
                const int row = idx >> 3, cc = idx & 7;
                CP_ASYNC16(b + row * LDS + cc * 16,
                           Af + (size_t)(m0 + row) * lda + kg + cc * 4);
            }
#pragma unroll
            for (int j = 0; j < 2; ++j) {                // B: 64 rows x 128B
                const int idx = tid + j * 256;
                const int row = idx >> 3, cc = idx & 7;
                CP_ASYNC16(b + BOFF + row * LDS + cc * 16,
                           Bf + (size_t)(n0 + row) * lda + kg + cc * 4);
            }
        } else {
            const bf16* Ah = (const bf16*)Ahv; const bf16* Al = (const bf16*)Alv;
            const bf16* Bh = (const bf16*)Bhv; const bf16* Bl = (const bf16*)Blv;
#pragma unroll
            for (int j = 0; j < 2; ++j) {
                const int idx = tid + j * 256;
                const int row = idx >> 2, cc = idx & 3;
                const size_t go = (size_t)(m0 + row) * lda + kg + cc * 8;
                const uint32_t so = b + row * LDS + cc * 16;
                CP_ASYNC16(so,         Ah + go);
                CP_ASYNC16(so + 10240, Al + go);
            }
            {
                const int row = tid >> 2, cc = tid & 3;
                const size_t go = (size_t)(n0 + row) * lda + kg + cc * 8;
                const uint32_t so = b + BOFF + row * LDS + cc * 16;
                CP_ASYNC16(so,        Bh + go);
                CP_ASYNC16(so + 5120, Bl + go);
            }
        }
        CP_COMMIT();
    };

    copy_chunk(0, 0);

    for (int c = 0; c < nchunks; ++c) {
        CP_WAIT0();
        __syncthreads();
        if (c + 1 < nchunks) copy_chunk(c + 1, (c + 1) & 1);

        const uint32_t b = sb + (c & 1) * BUFB;

        if (TF) {
            const uint32_t aA = b, aB = b + BOFF;
#pragma unroll
            for (int ks = 0; ks < 4; ++ks) {
                const int kb = ks * 32;                  // 8 tf32 = 32B
                uint32_t Af_[2][4];
                {
                    const int rowoff = ((sub & 1) << 3) + lr;
                    const int kboff  = kb + ((sub >> 1) << 4);
#pragma unroll
                    for (int mt = 0; mt < 2; ++mt)
                        ldsm4(aA + (uint32_t)((wm * 32 + mt * 16 + rowoff) * LDS + kboff),
                              Af_[mt]);
                }
                uint32_t Bf_[2][4];
                {
                    const int nrow  = ((sub >> 1) << 3) + lr;
                    const int kboff = kb + ((sub & 1) << 4);
#pragma unroll
                    for (int np = 0; np < 2; ++np)
                        ldsm4(aB + (uint32_t)((wn * 32 + np * 16 + nrow) * LDS + kboff),
                              Bf_[np]);
                }
#pragma unroll
                for (int mt = 0; mt < 2; ++mt)
#pragma unroll
                    for (int nt = 0; nt < 4; ++nt)
                        mma_tf(acc[mt][nt], Af_[mt],
                               Bf_[nt >> 1][(nt & 1) * 2],
                               Bf_[nt >> 1][(nt & 1) * 2 + 1]);
            }
        } else {
            const uint32_t aAh = b, aAl = b + 10240;
            const uint32_t aBh = b + BOFF, aBl = b + BOFF + 5120;
#pragma unroll
            for (int ks = 0; ks < 2; ++ks) {
                const int kb = ks * 32;
                uint32_t Afh[2][4], Afl[2][4];
                {
                    const int rowoff = ((sub & 1) << 3) + lr;
                    const int kboff  = kb + ((sub >> 1) << 4);
#pragma unroll
                    for (int mt = 0; mt < 2; ++mt) {
                        const uint32_t off =
                            (uint32_t)((wm * 32 + mt * 16 + rowoff) * LDS + kboff);
                        ldsm4(aAh + off, Afh[mt]);
                        ldsm4(aAl + off, Afl[mt]);
                    }
                }
                uint32_t Bfh[2][4], Bfl[2][4];
                {
                    const int nrow  = ((sub >> 1) << 3) + lr;
                    const int kboff = kb + ((sub & 1) << 4);
#pragma unroll
                    for (int np = 0; np < 2; ++np) {
                        const uint32_t off =
                            (uint32_t)((wn * 32 + np * 16 + nrow) * LDS + kboff);
                        ldsm4(aBh + off, Bfh[np]);
                        ldsm4(aBl + off, Bfl[np]);
                    }
                }
#pragma unroll
                for (int mt = 0; mt < 2; ++mt)
#pragma unroll
                    for (int nt = 0; nt < 4; ++nt) {
                        const uint32_t bh0 = Bfh[nt >> 1][(nt & 1) * 2];
                        const uint32_t bh1 = Bfh[nt >> 1][(nt & 1) * 2 + 1];
                        const uint32_t bl0 = Bfl[nt >> 1][(nt & 1) * 2];
                        const uint32_t bl1 = Bfl[nt >> 1][(nt & 1) * 2 + 1];
                        mma_bf(acc[mt][nt], Afh[mt], bh0, bh1);
                        mma_bf(acc[mt][nt], Afh[mt], bl0, bl1);
                        mma_bf(acc[mt][nt], Afl[mt], bh0, bh1);
                    }
            }
        }
    }

    // ---- epilogue ----
    const int tg = lane >> 2, tc = lane & 3;
#pragma unroll
    for (int mt = 0; mt < 2; ++mt) {
#pragma unroll
        for (int half = 0; half < 2; ++half) {
            const int m = m0 + wm * 32 + mt * 16 + tg + half * 8;
#pragma unroll
            for (int nt = 0; nt < 4; ++nt) {
                const int n = n0 + wn * 32 + nt * 8 + tc * 2;
                float v0 = acc[mt][nt][half * 2 + 0];
                float v1 = acc[mt][nt][half * 2 + 1];
                if (EPI == 0) {                      // x: +bias -> tf32 fp32
                    v0 = tf32r(v0 + e0[n]); v1 = tf32r(v1 + e0[n + 1]);
                    *reinterpret_cast<float2*>(C + (size_t)m * DM + n) =
                        make_float2(v0, v1);
                } else if (EPI == 1) {               // in_proj split
                    if (n < DI) {
                        v0 = siluf(v0 * e0[n * 4 + 3] + e1[n]);
                        v1 = siluf(v1 * e0[(n + 1) * 4 + 3] + e1[n + 1]);
                        *reinterpret_cast<float2*>(C + (size_t)m * DI + n) =
                            make_float2(v0, v1);
                        wsplit2(Ch, Cl, (size_t)m * DI + n, v0, v1);
                    } else {
                        *reinterpret_cast<float2*>(e2 + (size_t)m * DI + (n - DI)) =
                            make_float2(siluf(v0), siluf(v1));
                    }
                } else if (EPI == 3) {               // fused heads -> out
                    v0 += e0[n]; v1 += e0[n + 1];
                    if (n < ADIM) {
                        *reinterpret_cast<float2*>(e2 + (size_t)m * ADIM + n) =
                            make_float2(tanhf(v0), tanhf(v1));
                    } else {
                        v0 = fminf(fmaxf(v0, -5.f), 2.f);
                        v1 = fminf(fmaxf(v1, -5.f), 2.f);
                        *reinterpret_cast<float2*>(
                            e2 + (size_t)BATCH * ADIM + (size_t)m * ADIM + (n - ADIM)) =
                            make_float2(v0, v1);
                    }
                } else {                             // EPI 4: xdbl partial
                    if (n < 48)
                        *reinterpret_cast<float2*>(
                            C + (size_t)blockIdx.z * BATCH * 48 + (size_t)m * 48 + n) =
                            make_float2(v0, v1);
                }
            }
        }
    }
}

// ---------------- fused SSM pointwise -> Y bf16 planes ----------------
__global__ void __launch_bounds__(256)
mamba_pointwise(const float* __restrict__ xdbl, const float* __restrict__ dt_w,
                const float* __restrict__ dt_b, const float* __restrict__ Dskip,
                const float* __restrict__ U, const float* __restrict__ Zs,
                bf16* __restrict__ Yh, bf16* __restrict__ Yl)
{
    constexpr int NB = 16;
    __shared__ float s_xd[NB][48];
    __shared__ float s_bc[NB];
    const int b0 = blockIdx.x * NB;
    const int tid = threadIdx.x;

    for (int i = tid; i < NB * 48; i += 256) {
        const size_t off = (size_t)(b0 + i / 48) * 48 + (i % 48);
        s_xd[i / 48][i % 48] = xdbl[off] + xdbl[(size_t)BATCH * 48 + off];
    }
    __syncthreads();
    if (tid < NB) {
        float s = 0.f;
#pragma unroll
        for (int n = 0; n < DS; n++) s += s_xd[tid][16 + n] * s_xd[tid][32 + n];
        s_bc[tid] = s;
    }
    __syncthreads();

#pragma unroll 1
    for (int dd = 0; dd < DI / 256; dd++) {
        const int d = tid + dd * 256;
        const float4 w0 = *reinterpret_cast<const float4*>(dt_w + d * 16 + 0);
        const float4 w1 = *reinterpret_cast<const float4*>(dt_w + d * 16 + 4);
        const float4 w2 = *reinterpret_cast<const float4*>(dt_w + d * 16 + 8);
        const float4 w3 = *reinterpret_cast<const float4*>(dt_w + d * 16 + 12);
        const float bias = dt_b[d];
        const float dsk  = Dskip[d];
#pragma unroll
        for (int bb = 0; bb < NB; bb++) {
            const int b = b0 + bb;
            const float* xd = s_xd[bb];
            float a = bias;
            a = fmaf(w0.x, xd[0],  a); a = fmaf(w0.y, xd[1],  a);
            a = fmaf(w0.z, xd[2],  a); a = fmaf(w0.w, xd[3],  a);
            a = fmaf(w1.x, xd[4],  a); a = fmaf(w1.y, xd[5],  a);
            a = fmaf(w1.z, xd[6],  a); a = fmaf(w1.w, xd[7],  a);
            a = fmaf(w2.x, xd[8],  a); a = fmaf(w2.y, xd[9],  a);
            a = fmaf(w2.z, xd[10], a); a = fmaf(w2.w, xd[11], a);
            a = fmaf(w3.x, xd[12], a); a = fmaf(w3.y, xd[13], a);
            a = fmaf(w3.z, xd[14], a); a = fmaf(w3.w, xd[15], a);
            const float delta = softplusf(a);
            const float u = U[(size_t)b * DI + d];
            const float y = u * fmaf(delta, s_bc[bb], dsk) * Zs[(size_t)b * DI + d];
            wsplit1(Yh, Yl, (size_t)b * DI + d, y);
        }
    }
}

// ---------------- weight prep ----------------
__global__ void prep(const float* __restrict__ W_in, const float* __restrict__ ip,
                     const float* __restrict__ xp,
                     const float* __restrict__ mu_b, const float* __restrict__ ls_b,
                     float* __restrict__ hb)
{
    const int i = blockIdx.x * 256 + threadIdx.x;       // 0..425983
    if (i < 131072) {
        wsplit1(g_Winh, g_Winl, i, W_in[i]);
    } else if (i < 393216) {
        const int j = i - 131072;
        g_ipt[j] = tf32r(ip[j]);                        // tf32-rounded fp32
    } else if (i < 425984) {
        const int j = i - 393216;
        wsplit1(g_xph, g_xpl, j, (j < 48 * DI) ? xp[j] : 0.f);
    }
    if (i < 128) hb[i] = (i < ADIM) ? mu_b[i] : ls_b[i - ADIM];
}

// ---------------- fused head weight: Whc = [mu_w;ls_w] @ out_proj ----------------
__global__ void __launch_bounds__(512)
fuse_heads(const float* __restrict__ mu_w, const float* __restrict__ ls_w,
           const float* __restrict__ op)
{
    const int i = blockIdx.x;            // 0..127
    const int j = threadIdx.x;           // 0..511
    const float* wrow = (i < ADIM) ? (mu_w + (size_t)i * DM)
                                   : (ls_w + (size_t)(i - ADIM) * DM);
    float s = 0.f;
#pragma unroll 8
    for (int k = 0; k < DM; ++k)
        s = fmaf(wrow[k], op[(size_t)k * DI + j], s);
    wsplit1(g_hwch, g_hwcl, (size_t)i * DI + j, s);
}

// ---------------- perception -> planes ----------------
__global__ void conv_perc(const float* __restrict__ src)
{
    const size_t i = ((size_t)blockIdx.x * 256 + threadIdx.x) * 4;
    const float4 v = *reinterpret_cast<const float4*>(src + i);
    wsplit2(g_ph, g_pl, i,     v.x, v.y);
    wsplit2(g_ph, g_pl, i + 2, v.z, v.w);
}

// ---------------- launch ----------------
#define GSMEM_BF (2 * 30720)    // 61440
#define GSMEM_TF (2 * 27648)    // 55296

extern "C" void kernel_launch(void* const* d_in, const int* in_sizes, int n_in,
                              void* d_out, int out_size)
{
    const float* perception = (const float*)d_in[0];
    const float* W_in       = (const float*)d_in[1];
    const float* b_in       = (const float*)d_in[2];
    const float* mu_w       = (const float*)d_in[3];
    const float* mu_b       = (const float*)d_in[4];
    const float* ls_w       = (const float*)d_in[5];
    const float* ls_b       = (const float*)d_in[6];
    const float* in_proj_w  = (const float*)d_in[7];
    const float* conv_w     = (const float*)d_in[8];
    const float* conv_b     = (const float*)d_in[9];
    const float* x_proj_w   = (const float*)d_in[10];
    const float* dt_proj_w  = (const float*)d_in[11];
    const float* dt_proj_b  = (const float*)d_in[12];
    const float* Dskip      = (const float*)d_in[14];
    const float* out_proj_w = (const float*)d_in[15];
    float* out = (float*)d_out;

    float *pU, *pZs, *pxd, *phb, *pxt, *pipt;
    cudaGetSymbolAddress((void**)&pU,  g_U);
    cudaGetSymbolAddress((void**)&pZs, g_Zs);
    cudaGetSymbolAddress((void**)&pxd, g_xd);
    cudaGetSymbolAddress((void**)&phb, g_hb);
    cudaGetSymbolAddress((void**)&pxt, g_xt);
    cudaGetSymbolAddress((void**)&pipt,g_ipt);

    bf16 *ph_, *pl_, *Uh, *Ul, *Yh, *Yl;
    bf16 *Wh, *Wl, *xph_, *xpl_, *hwch, *hwcl;
    cudaGetSymbolAddress((void**)&ph_, g_ph);  cudaGetSymbolAddress((void**)&pl_, g_pl);
    cudaGetSymbolAddress((void**)&Uh,  g_Uh);  cudaGetSymbolAddress((void**)&Ul,  g_Ul);
    cudaGetSymbolAddress((void**)&Yh,  g_Yh);  cudaGetSymbolAddress((void**)&Yl,  g_Yl);
    cudaGetSymbolAddress((void**)&Wh,  g_Winh);cudaGetSymbolAddress((void**)&Wl,  g_Winl);
    cudaGetSymbolAddress((void**)&xph_,g_xph); cudaGetSymbolAddress((void**)&xpl_,g_xpl);
    cudaGetSymbolAddress((void**)&hwch,g_hwch);cudaGetSymbolAddress((void**)&hwcl,g_hwcl);

    cudaFuncSetAttribute((const void*)mma_gemm<0,0>, cudaFuncAttributeMaxDynamicSharedMemorySize, GSMEM_BF);
    cudaFuncSetAttribute((const void*)mma_gemm<1,2>, cudaFuncAttributeMaxDynamicSharedMemorySize, GSMEM_TF);
    cudaFuncSetAttribute((const void*)mma_gemm<3,0>, cudaFuncAttributeMaxDynamicSharedMemorySize, GSMEM_BF);
    cudaFuncSetAttribute((const void*)mma_gemm<4,0>, cudaFuncAttributeMaxDynamicSharedMemorySize, GSMEM_BF);

    // 0) prep: weight splits + tf32 weights, fused head weight, perception split
    prep<<<1664, 256>>>(W_in, in_proj_w, x_proj_w, mu_b, ls_b, phb);
    fuse_heads<<<128, 512>>>(mu_w, ls_w, out_proj_w);
    conv_perc<<<4096, 256>>>(perception);

    // 1) x = perc @ W_in^T + b        (bf16x3, K=512) -> x tf32 fp32
    mma_gemm<0,0><<<dim3(4, 64), 256, GSMEM_BF>>>(
        ph_, pl_, Wh, Wl, P_DIM, P_DIM, pxt, b_in, nullptr, nullptr, nullptr, nullptr);

    // 2) xz = x @ in_proj^T           (tf32x1, N=1024, K=256) -> U / Zs
    mma_gemm<1,2><<<dim3(16, 64), 256, GSMEM_TF>>>(
        pxt, nullptr, pipt, nullptr, DM, DM, pU, conv_w, conv_b, pZs, Uh, Ul);

    // 3) x_dbl partials, split-K=2    (bf16x3, K=256 each, lda=512)
    mma_gemm<4,0><<<dim3(1, 64, 2), 256, GSMEM_BF>>>(
        Uh, Ul, xph_, xpl_, 256, DI, pxd, nullptr, nullptr, nullptr, nullptr, nullptr);

    // 4) pointwise -> Y planes
    mamba_pointwise<<<BATCH / 16, 256>>>(pxd, dt_proj_w, dt_proj_b, Dskip,
                                         pU, pZs, Yh, Yl);

    // 5) fused heads: [mu|log_std] = Y @ Whc^T + hb  (bf16x3, K=512) -> out
    mma_gemm<3,0><<<dim3(2, 64), 256, GSMEM_BF>>>(
        Yh, Yl, hwch, hwcl, DI, DI, nullptr, phb, nullptr, out, nullptr, nullptr);
}

// round 15
// speedup vs baseline: 1.2127x; 1.1084x over previous
#include <cuda_runtime.h>
#include <cuda_bf16.h>
#include <math.h>
#include <stdint.h>

#define BATCH   8192
#define P_DIM   512
#define DM      256     // D_MODEL
#define DI      512     // D_INNER
#define DS      16
#define ADIM    64

typedef __nv_bfloat16 bf16;

// ---------------- fp32 scratch ----------------
__device__ float g_U  [BATCH * DI];
__device__ float g_Zs [BATCH * DI];
__device__ float g_xd [2 * BATCH * 48];        // split-K partials
__device__ float g_hb [128];
__device__ __align__(256) float g_xt  [BATCH * DM];    // x, tf32-rounded fp32
__device__ __align__(256) float g_Ut  [BATCH * DI];    // U, tf32-rounded fp32
__device__ __align__(256) float g_Wint[DM * P_DIM];    // W_in, tf32-rounded
__device__ __align__(256) float g_ipt [2 * DI * DM];   // in_proj_w, tf32-rounded
__device__ __align__(256) float g_xpt [64 * DI];       // x_proj padded, tf32-rounded

// ---------------- bf16 hi/lo planes (heads GEMM only) ----------------
__device__ __align__(256) bf16 g_Yh[BATCH * DI],  g_Yl[BATCH * DI];
__device__ __align__(256) bf16 g_hwch[128 * DI],  g_hwcl[128 * DI];

__device__ __forceinline__ float siluf(float x) { return x / (1.f + __expf(-x)); }
__device__ __forceinline__ float softplusf(float x) {
    return (x > 20.f) ? x : log1pf(__expf(x));
}
__device__ __forceinline__ float tf32r(float v) {
    uint32_t r;
    asm("cvt.rna.tf32.f32 %0, %1;" : "=r"(r) : "f"(v));
    return __uint_as_float(r);
}
__device__ __forceinline__ uint32_t smem_u32(const void* p) {
    uint32_t a;
    asm("{ .reg .u64 t; cvta.to.shared.u64 t, %1; cvt.u32.u64 %0, t; }"
        : "=r"(a) : "l"(p));
    return a;
}
__device__ __forceinline__ void ldsm4(uint32_t addr, uint32_t r[4]) {
    asm volatile("ldmatrix.sync.aligned.m8n8.x4.shared.b16 {%0,%1,%2,%3}, [%4];"
                 : "=r"(r[0]), "=r"(r[1]), "=r"(r[2]), "=r"(r[3]) : "r"(addr));
}
__device__ __forceinline__ void mma_bf(float c[4], const uint32_t a[4],
                                       uint32_t b0, uint32_t b1) {
    asm volatile(
        "mma.sync.aligned.m16n8k16.row.col.f32.bf16.bf16.f32 "
        "{%0,%1,%2,%3}, {%4,%5,%6,%7}, {%8,%9}, {%0,%1,%2,%3};"
        : "+f"(c[0]), "+f"(c[1]), "+f"(c[2]), "+f"(c[3])
        : "r"(a[0]), "r"(a[1]), "r"(a[2]), "r"(a[3]), "r"(b0), "r"(b1));
}
__device__ __forceinline__ void mma_tf(float c[4], const uint32_t a[4],
                                       uint32_t b0, uint32_t b1) {
    asm volatile(
        "mma.sync.aligned.m16n8k8.row.col.f32.tf32.tf32.f32 "
        "{%0,%1,%2,%3}, {%4,%5,%6,%7}, {%8,%9}, {%0,%1,%2,%3};"
        : "+f"(c[0]), "+f"(c[1]), "+f"(c[2]), "+f"(c[3])
        : "r"(a[0]), "r"(a[1]), "r"(a[2]), "r"(a[3]), "r"(b0), "r"(b1));
}
#define CP_ASYNC16(dst, src) \
    asm volatile("cp.async.cg.shared.global [%0], [%1], 16;" :: "r"(dst), "l"(src))
#define CP_COMMIT()  asm volatile("cp.async.commit_group;" ::: "memory")
#define CP_WAIT0()   asm volatile("cp.async.wait_group 0;" ::: "memory")

__device__ __forceinline__ void wsplit2(bf16* H, bf16* L, size_t off,
                                        float v0, float v1) {
    bf16 h0 = __float2bfloat16(v0), h1 = __float2bfloat16(v1);
    bf16 l0 = __float2bfloat16(v0 - __bfloat162float(h0));
    bf16 l1 = __float2bfloat16(v1 - __bfloat162float(h1));
    *reinterpret_cast<__nv_bfloat162*>(H + off) = __halves2bfloat162(h0, h1);
    *reinterpret_cast<__nv_bfloat162*>(L + off) = __halves2bfloat162(l0, l1);
}
__device__ __forceinline__ void wsplit1(bf16* H, bf16* L, size_t off, float v) {
    bf16 h = __float2bfloat16(v);
    H[off] = h;
    L[off] = __float2bfloat16(v - __bfloat162float(h));
}

// ====== tensor GEMM: C[m,n] = sum_k A[m,k] * W[n,k] ======
// Tile 128(M) x 64(N) x 32(K). 256 thr = 8 warps (4m x 2n), 32x32/warp.
// 2-stage cp.async pipeline.
// PREC 0: bf16x3 (A/B hi+lo planes, 3 MMA/acc/k16)
// PREC 2: tf32x1 (A/B fp32, tf32 MMA truncates/pre-rounded, 1 MMA/acc/k8)
// EPI: 0 +bias -> tf32 x | 1 in_proj split (U fp32 + U tf32) | 3 fused heads -> out
//      4 xdbl partial (grid.z split, n<48)
template<int EPI, int PREC>
__global__ void __launch_bounds__(256)
mma_gemm(const void* __restrict__ Ahv, const void* __restrict__ Alv,
         const void* __restrict__ Bhv, const void* __restrict__ Blv,
         int K, int lda,
         float* __restrict__ C, const float* __restrict__ e0,
         const float* __restrict__ e1, float* __restrict__ e2,
         void* __restrict__ Ch, void* __restrict__ Cl)
{
    constexpr bool TF   = (PREC == 2);
    constexpr int  LDS  = TF ? 144 : 80;
    constexpr int  BOFF = TF ? 18432 : 20480;          // B region start
    constexpr int  BUFB = TF ? 27648 : 30720;          // bytes per stage

    extern __shared__ __align__(16) uint8_t dsm[];
    const uint32_t sb = smem_u32(dsm);

    const int tid  = threadIdx.x;
    const int lane = tid & 31, wid = tid >> 5;
    const int wm = wid & 3, wn = wid >> 2;
    const int m0 = blockIdx.y * 128, n0 = blockIdx.x * 64;
    const int kOff = blockIdx.z * K;
    const int lr = lane & 7, sub = lane >> 3;

    float acc[2][4][4];
#pragma unroll
    for (int i = 0; i < 2; i++)
#pragma unroll
        for (int j = 0; j < 4; j++)
#pragma unroll
            for (int l = 0; l < 4; l++) acc[i][j][l] = 0.f;

    const int nchunks = K >> 5;

    auto copy_chunk = [&](int c, int buf) {
        const int kg = kOff + (c << 5);
        const uint32_t b = sb + buf * BUFB;
        if (TF) {
            const float* Af = (const float*)Ahv;
            const float* Bf = (const float*)Bhv;
#pragma unroll
            for (int j = 0; j < 4; ++j) {                // A: 128 rows x 128B
                const int idx = tid + j * 256;
                const int row = idx >> 3, cc = idx & 7;
                CP_ASYNC16(b + row * LDS + cc * 16,
                           Af + (size_t)(m0 + row) * lda + kg + cc * 4);
            }
#pragma unroll
            for (int j = 0; j < 2; ++j) {                // B: 64 rows x 128B
                const int idx = tid + j * 256;
                const int row = idx >> 3, cc = idx & 7;
                CP_ASYNC16(b + BOFF + row * LDS + cc * 16,
                           Bf + (size_t)(n0 + row) * lda + kg + cc * 4);
            }
        } else {
            const bf16* Ah = (const bf16*)Ahv; const bf16* Al = (const bf16*)Alv;
            const bf16* Bh = (const bf16*)Bhv; const bf16* Bl = (const bf16*)Blv;
#pragma unroll
            for (int j = 0; j < 2; ++j) {
                const int idx = tid + j * 256;
                const int row = idx >> 2, cc = idx & 3;
                const size_t go = (size_t)(m0 + row) * lda + kg + cc * 8;
                const uint32_t so = b + row * LDS + cc * 16;
                CP_ASYNC16(so,         Ah + go);
                CP_ASYNC16(so + 10240, Al + go);
            }
            {
                const int row = tid >> 2, cc = tid & 3;
                const size_t go = (size_t)(n0 + row) * lda + kg + cc * 8;
                const uint32_t so = b + BOFF + row * LDS + cc * 16;
                CP_ASYNC16(so,        Bh + go);
                CP_ASYNC16(so + 5120, Bl + go);
            }
        }
        CP_COMMIT();
    };

    copy_chunk(0, 0);

    for (int c = 0; c < nchunks; ++c) {
        CP_WAIT0();
        __syncthreads();
        if (c + 1 < nchunks) copy_chunk(c + 1, (c + 1) & 1);

        const uint32_t b = sb + (c & 1) * BUFB;

        if (TF) {
            const uint32_t aA = b, aB = b + BOFF;
#pragma unroll
            for (int ks = 0; ks < 4; ++ks) {
                const int kb = ks * 32;                  // 8 tf32 = 32B
                uint32_t Af_[2][4];
                {
                    const int rowoff = ((sub & 1) << 3) + lr;
                    const int kboff  = kb + ((sub >> 1) << 4);
#pragma unroll
                    for (int mt = 0; mt < 2; ++mt)
                        ldsm4(aA + (uint32_t)((wm * 32 + mt * 16 + rowoff) * LDS + kboff),
                              Af_[mt]);
                }
                uint32_t Bf_[2][4];
                {
                    const int nrow  = ((sub >> 1) << 3) + lr;
                    const int kboff = kb + ((sub & 1) << 4);
#pragma unroll
                    for (int np = 0; np < 2; ++np)
                        ldsm4(aB + (uint32_t)((wn * 32 + np * 16 + nrow) * LDS + kboff),
                              Bf_[np]);
                }
#pragma unroll
                for (int mt = 0; mt < 2; ++mt)
#pragma unroll
                    for (int nt = 0; nt < 4; ++nt)
                        mma_tf(acc[mt][nt], Af_[mt],
                               Bf_[nt >> 1][(nt & 1) * 2],
                               Bf_[nt >> 1][(nt & 1) * 2 + 1]);
            }
        } else {
            const uint32_t aAh = b, aAl = b + 10240;
            const uint32_t aBh = b + BOFF, aBl = b + BOFF + 5120;
#pragma unroll
            for (int ks = 0; ks < 2; ++ks) {
                const int kb = ks * 32;
                uint32_t Afh[2][4], Afl[2][4];
                {
                    const int rowoff = ((sub & 1) << 3) + lr;
                    const int kboff  = kb + ((sub >> 1) << 4);
#pragma unroll
                    for (int mt = 0; mt < 2; ++mt) {
                        const uint32_t off =
                            (uint32_t)((wm * 32 + mt * 16 + rowoff) * LDS + kboff);
                        ldsm4(aAh + off, Afh[mt]);
                        ldsm4(aAl + off, Afl[mt]);
                    }
                }
                uint32_t Bfh[2][4], Bfl[2][4];
                {
                    const int nrow  = ((sub >> 1) << 3) + lr;
                    const int kboff = kb + ((sub & 1) << 4);
#pragma unroll
                    for (int np = 0; np < 2; ++np) {
                        const uint32_t off =
                            (uint32_t)((wn * 32 + np * 16 + nrow) * LDS + kboff);
                        ldsm4(aBh + off, Bfh[np]);
                        ldsm4(aBl + off, Bfl[np]);
                    }
                }
#pragma unroll
                for (int mt = 0; mt < 2; ++mt)
#pragma unroll
                    for (int nt = 0; nt < 4; ++nt) {
                        const uint32_t bh0 = Bfh[nt >> 1][(nt & 1) * 2];
                        const uint32_t bh1 = Bfh[nt >> 1][(nt & 1) * 2 + 1];
                        const uint32_t bl0 = Bfl[nt >> 1][(nt & 1) * 2];
                        const uint32_t bl1 = Bfl[nt >> 1][(nt & 1) * 2 + 1];
                        mma_bf(acc[mt][nt], Afh[mt], bh0, bh1);
                        mma_bf(acc[mt][nt], Afh[mt], bl0, bl1);
                        mma_bf(acc[mt][nt], Afl[mt], bh0, bh1);
                    }
            }
        }
    }

    // ---- epilogue ----
    const int tg = lane >> 2, tc = lane & 3;
#pragma unroll
    for (int mt = 0; mt < 2; ++mt) {
#pragma unroll
        for (int half = 0; half < 2; ++half) {
            const int m = m0 + wm * 32 + mt * 16 + tg + half * 8;
#pragma unroll
            for (int nt = 0; nt < 4; ++nt) {
                const int n = n0 + wn * 32 + nt * 8 + tc * 2;
                float v0 = acc[mt][nt][half * 2 + 0];
                float v1 = acc[mt][nt][half * 2 + 1];
                if (EPI == 0) {                      // x: +bias -> tf32 fp32
                    v0 = tf32r(v0 + e0[n]); v1 = tf32r(v1 + e0[n + 1]);
                    *reinterpret_cast<float2*>(C + (size_t)m * DM + n) =
                        make_float2(v0, v1);
                } else if (EPI == 1) {               // in_proj split
                    if (n < DI) {
                        v0 = siluf(v0 * e0[n * 4 + 3] + e1[n]);
                        v1 = siluf(v1 * e0[(n + 1) * 4 + 3] + e1[n + 1]);
                        *reinterpret_cast<float2*>(C + (size_t)m * DI + n) =
                            make_float2(v0, v1);
                        *reinterpret_cast<float2*>((float*)Ch + (size_t)m * DI + n) =
                            make_float2(tf32r(v0), tf32r(v1));
                    } else {
                        *reinterpret_cast<float2*>(e2 + (size_t)m * DI + (n - DI)) =
                            make_float2(siluf(v0), siluf(v1));
                    }
                } else if (EPI == 3) {               // fused heads -> out
                    v0 += e0[n]; v1 += e0[n + 1];
                    if (n < ADIM) {
                        *reinterpret_cast<float2*>(e2 + (size_t)m * ADIM + n) =
                            make_float2(tanhf(v0), tanhf(v1));
                    } else {
                        v0 = fminf(fmaxf(v0, -5.f), 2.f);
                        v1 = fminf(fmaxf(v1, -5.f), 2.f);
                        *reinterpret_cast<float2*>(
                            e2 + (size_t)BATCH * ADIM + (size_t)m * ADIM + (n - ADIM)) =
                            make_float2(v0, v1);
                    }
                } else {                             // EPI 4: xdbl partial
                    if (n < 48)
                        *reinterpret_cast<float2*>(
                            C + (size_t)blockIdx.z * BATCH * 48 + (size_t)m * 48 + n) =
                            make_float2(v0, v1);
                }
            }
        }
    }
}

// ---------------- fused SSM pointwise -> Y bf16 planes ----------------
__global__ void __launch_bounds__(256)
mamba_pointwise(const float* __restrict__ xdbl, const float* __restrict__ dt_w,
                const float* __restrict__ dt_b, const float* __restrict__ Dskip,
                const float* __restrict__ U, const float* __restrict__ Zs,
                bf16* __restrict__ Yh, bf16* __restrict__ Yl)
{
    constexpr int NB = 16;
    __shared__ float s_xd[NB][48];
    __shared__ float s_bc[NB];
    const int b0 = blockIdx.x * NB;
    const int tid = threadIdx.x;

    for (int i = tid; i < NB * 48; i += 256) {
        const size_t off = (size_t)(b0 + i / 48) * 48 + (i % 48);
        s_xd[i / 48][i % 48] = xdbl[off] + xdbl[(size_t)BATCH * 48 + off];
    }
    __syncthreads();
    if (tid < NB) {
        float s = 0.f;
#pragma unroll
        for (int n = 0; n < DS; n++) s += s_xd[tid][16 + n] * s_xd[tid][32 + n];
        s_bc[tid] = s;
    }
    __syncthreads();

#pragma unroll 1
    for (int dd = 0; dd < DI / 256; dd++) {
        const int d = tid + dd * 256;
        const float4 w0 = *reinterpret_cast<const float4*>(dt_w + d * 16 + 0);
        const float4 w1 = *reinterpret_cast<const float4*>(dt_w + d * 16 + 4);
        const float4 w2 = *reinterpret_cast<const float4*>(dt_w + d * 16 + 8);
        const float4 w3 = *reinterpret_cast<const float4*>(dt_w + d * 16 + 12);
        const float bias = dt_b[d];
        const float dsk  = Dskip[d];
#pragma unroll
        for (int bb = 0; bb < NB; bb++) {
            const int b = b0 + bb;
            const float* xd = s_xd[bb];
            float a = bias;
            a = fmaf(w0.x, xd[0],  a); a = fmaf(w0.y, xd[1],  a);
            a = fmaf(w0.z, xd[2],  a); a = fmaf(w0.w, xd[3],  a);
            a = fmaf(w1.x, xd[4],  a); a = fmaf(w1.y, xd[5],  a);
            a = fmaf(w1.z, xd[6],  a); a = fmaf(w1.w, xd[7],  a);
            a = fmaf(w2.x, xd[8],  a); a = fmaf(w2.y, xd[9],  a);
            a = fmaf(w2.z, xd[10], a); a = fmaf(w2.w, xd[11], a);
            a = fmaf(w3.x, xd[12], a); a = fmaf(w3.y, xd[13], a);
            a = fmaf(w3.z, xd[14], a); a = fmaf(w3.w, xd[15], a);
            const float delta = softplusf(a);
            const float u = U[(size_t)b * DI + d];
            const float y = u * fmaf(delta, s_bc[bb], dsk) * Zs[(size_t)b * DI + d];
            wsplit1(Yh, Yl, (size_t)b * DI + d, y);
        }
    }
}

// ---------------- weight prep: tf32-round W_in / in_proj / x_proj ----------------
__global__ void prep(const float* __restrict__ W_in, const float* __restrict__ ip,
                     const float* __restrict__ xp,
                     const float* __restrict__ mu_b, const float* __restrict__ ls_b,
                     float* __restrict__ hb)
{
    const int i = blockIdx.x * 256 + threadIdx.x;       // 0..425983
    if (i < 131072) {
        g_Wint[i] = tf32r(W_in[i]);
    } else if (i < 393216) {
        const int j = i - 131072;
        g_ipt[j] = tf32r(ip[j]);
    } else if (i < 425984) {
        const int j = i - 393216;
        g_xpt[j] = (j < 48 * DI) ? tf32r(xp[j]) : 0.f;
    }
    if (i < 128) hb[i] = (i < ADIM) ? mu_b[i] : ls_b[i - ADIM];
}

// ---------------- fused head weight: Whc = [mu_w;ls_w] @ out_proj ----------------
__global__ void __launch_bounds__(512)
fuse_heads(const float* __restrict__ mu_w, const float* __restrict__ ls_w,
           const float* __restrict__ op)
{
    const int i = blockIdx.x;            // 0..127
    const int j = threadIdx.x;           // 0..511
    const float* wrow = (i < ADIM) ? (mu_w + (size_t)i * DM)
                                   : (ls_w + (size_t)(i - ADIM) * DM);
    float s = 0.f;
#pragma unroll 8
    for (int k = 0; k < DM; ++k)
        s = fmaf(wrow[k], op[(size_t)k * DI + j], s);
    wsplit1(g_hwch, g_hwcl, (size_t)i * DI + j, s);
}

// ---------------- launch ----------------
#define GSMEM_BF (2 * 30720)    // 61440
#define GSMEM_TF (2 * 27648)    // 55296

extern "C" void kernel_launch(void* const* d_in, const int* in_sizes, int n_in,
                              void* d_out, int out_size)
{
    const float* perception = (const float*)d_in[0];
    const float* W_in       = (const float*)d_in[1];
    const float* b_in       = (const float*)d_in[2];
    const float* mu_w       = (const float*)d_in[3];
    const float* mu_b       = (const float*)d_in[4];
    const float* ls_w       = (const float*)d_in[5];
    const float* ls_b       = (const float*)d_in[6];
    const float* in_proj_w  = (const float*)d_in[7];
    const float* conv_w     = (const float*)d_in[8];
    const float* conv_b     = (const float*)d_in[9];
    const float* x_proj_w   = (const float*)d_in[10];
    const float* dt_proj_w  = (const float*)d_in[11];
    const float* dt_proj_b  = (const float*)d_in[12];
    const float* Dskip      = (const float*)d_in[14];
    const float* out_proj_w = (const float*)d_in[15];
    float* out = (float*)d_out;

    float *pU, *pZs, *pxd, *phb, *pxt, *pUt, *pWint, *pipt, *pxpt;
    cudaGetSymbolAddress((void**)&pU,   g_U);
    cudaGetSymbolAddress((void**)&pZs,  g_Zs);
    cudaGetSymbolAddress((void**)&pxd,  g_xd);
    cudaGetSymbolAddress((void**)&phb,  g_hb);
    cudaGetSymbolAddress((void**)&pxt,  g_xt);
    cudaGetSymbolAddress((void**)&pUt,  g_Ut);
    cudaGetSymbolAddress((void**)&pWint,g_Wint);
    cudaGetSymbolAddress((void**)&pipt, g_ipt);
    cudaGetSymbolAddress((void**)&pxpt, g_xpt);

    bf16 *Yh, *Yl, *hwch, *hwcl;
    cudaGetSymbolAddress((void**)&Yh,  g_Yh);  cudaGetSymbolAddress((void**)&Yl,  g_Yl);
    cudaGetSymbolAddress((void**)&hwch,g_hwch);cudaGetSymbolAddress((void**)&hwcl,g_hwcl);

    cudaFuncSetAttribute((const void*)mma_gemm<0,2>, cudaFuncAttributeMaxDynamicSharedMemorySize, GSMEM_TF);
    cudaFuncSetAttribute((const void*)mma_gemm<1,2>, cudaFuncAttributeMaxDynamicSharedMemorySize, GSMEM_TF);
    cudaFuncSetAttribute((const void*)mma_gemm<3,0>, cudaFuncAttributeMaxDynamicSharedMemorySize, GSMEM_BF);
    cudaFuncSetAttribute((const void*)mma_gemm<4,2>, cudaFuncAttributeMaxDynamicSharedMemorySize, GSMEM_TF);

    // 0) prep: tf32 weights + fused head weight
    prep<<<1664, 256>>>(W_in, in_proj_w, x_proj_w, mu_b, ls_b, phb);
    fuse_heads<<<128, 512>>>(mu_w, ls_w, out_proj_w);

    // 1) x = perc @ W_in^T + b        (tf32x1, K=512; A = raw perception) -> x tf32
    mma_gemm<0,2><<<dim3(4, 64), 256, GSMEM_TF>>>(
        perception, nullptr, pWint, nullptr, P_DIM, P_DIM, pxt, b_in,
        nullptr, nullptr, nullptr, nullptr);

    // 2) xz = x @ in_proj^T           (tf32x1, N=1024, K=256) -> U fp32 + U tf32 / Zs
    mma_gemm<1,2><<<dim3(16, 64), 256, GSMEM_TF>>>(
        pxt, nullptr, pipt, nullptr, DM, DM, pU, conv_w, conv_b, pZs, pUt, nullptr);

    // 3) x_dbl partials, split-K=2    (tf32x1, K=256 each, lda=512)
    mma_gemm<4,2><<<dim3(1, 64, 2), 256, GSMEM_TF>>>(
        pUt, nullptr, pxpt, nullptr, 256, DI, pxd, nullptr, nullptr, nullptr,
        nullptr, nullptr);

    // 4) pointwise -> Y bf16 planes
    mamba_pointwise<<<BATCH / 16, 256>>>(pxd, dt_proj_w, dt_proj_b, Dskip,
                                         pU, pZs, Yh, Yl);

    // 5) fused heads: [mu|log_std] = Y @ Whc^T + hb  (bf16x3, K=512) -> out
    mma_gemm<3,0><<<dim3(2, 64), 256, GSMEM_BF>>>(
        Yh, Yl, hwch, hwcl, DI, DI, nullptr, phb, nullptr, out, nullptr, nullptr);
}